// round 1
// baseline (speedup 1.0000x reference)
#include <cuda_runtime.h>

// FocalBCELoss: loss = mean( -( t*log(p)*(1-p)^2*alpha[c] + (1-t)*log(1-p)*p^2 ) )
// N = 262144, C = 64, GAMMA = 2 (so pow -> square)

#define N_ROWS   262144
#define N_COLS   64
#define TOTAL    (N_ROWS * N_COLS)          // 16,777,216 elements
#define TOTAL4   (TOTAL / 4)                // 4,194,304 float4s
#define NBLOCKS  1184                       // 148 SMs * 8
#define NTHREADS 256

__device__ float g_partials[NBLOCKS];

__global__ __launch_bounds__(NTHREADS) void focal_partial_kernel(
    const float* __restrict__ inputs,
    const float* __restrict__ targets,
    const float* __restrict__ alpha)
{
    __shared__ float s_alpha[N_COLS];
    __shared__ float s_warp[NTHREADS / 32];

    int tid = threadIdx.x;
    if (tid < N_COLS) s_alpha[tid] = alpha[tid];
    __syncthreads();

    const float4* in4 = (const float4*)inputs;
    const float4* tg4 = (const float4*)targets;

    float acc = 0.0f;

    // grid-stride over float4 elements
    for (int i = blockIdx.x * NTHREADS + tid; i < TOTAL4; i += NBLOCKS * NTHREADS) {
        float4 p = in4[i];
        float4 t = tg4[i];
        int c0 = (i * 4) & (N_COLS - 1);   // column of first lane of this float4

        float a0 = s_alpha[c0 + 0];
        float a1 = s_alpha[c0 + 1];
        float a2 = s_alpha[c0 + 2];
        float a3 = s_alpha[c0 + 3];

        // element 0
        {
            float q = 1.0f - p.x;
            float left  = t.x * __logf(p.x) * q * q * a0;
            float right = (1.0f - t.x) * __logf(q) * p.x * p.x;
            acc -= left + right;
        }
        // element 1
        {
            float q = 1.0f - p.y;
            float left  = t.y * __logf(p.y) * q * q * a1;
            float right = (1.0f - t.y) * __logf(q) * p.y * p.y;
            acc -= left + right;
        }
        // element 2
        {
            float q = 1.0f - p.z;
            float left  = t.z * __logf(p.z) * q * q * a2;
            float right = (1.0f - t.z) * __logf(q) * p.z * p.z;
            acc -= left + right;
        }
        // element 3
        {
            float q = 1.0f - p.w;
            float left  = t.w * __logf(p.w) * q * q * a3;
            float right = (1.0f - t.w) * __logf(q) * p.w * p.w;
            acc -= left + right;
        }
    }

    // warp reduce
    #pragma unroll
    for (int off = 16; off > 0; off >>= 1)
        acc += __shfl_down_sync(0xFFFFFFFFu, acc, off);

    int lane = tid & 31;
    int wid  = tid >> 5;
    if (lane == 0) s_warp[wid] = acc;
    __syncthreads();

    if (wid == 0) {
        float v = (lane < NTHREADS / 32) ? s_warp[lane] : 0.0f;
        #pragma unroll
        for (int off = 16; off > 0; off >>= 1)
            v += __shfl_down_sync(0xFFFFFFFFu, v, off);
        if (lane == 0) g_partials[blockIdx.x] = v;
    }
}

__global__ __launch_bounds__(1024) void focal_finish_kernel(float* __restrict__ out)
{
    __shared__ float s_warp[32];
    int tid = threadIdx.x;

    float acc = 0.0f;
    for (int i = tid; i < NBLOCKS; i += 1024)
        acc += g_partials[i];

    #pragma unroll
    for (int off = 16; off > 0; off >>= 1)
        acc += __shfl_down_sync(0xFFFFFFFFu, acc, off);

    int lane = tid & 31;
    int wid  = tid >> 5;
    if (lane == 0) s_warp[wid] = acc;
    __syncthreads();

    if (wid == 0) {
        float v = (lane < 32) ? s_warp[lane] : 0.0f;
        #pragma unroll
        for (int off = 16; off > 0; off >>= 1)
            v += __shfl_down_sync(0xFFFFFFFFu, v, off);
        if (lane == 0) out[0] = v * (1.0f / (float)TOTAL);
    }
}

extern "C" void kernel_launch(void* const* d_in, const int* in_sizes, int n_in,
                              void* d_out, int out_size)
{
    const float* inputs  = (const float*)d_in[0];
    const float* targets = (const float*)d_in[1];
    const float* alpha   = (const float*)d_in[2];
    float* out = (float*)d_out;

    focal_partial_kernel<<<NBLOCKS, NTHREADS>>>(inputs, targets, alpha);
    focal_finish_kernel<<<1, 1024>>>(out);
}

// round 2
// speedup vs baseline: 1.0070x; 1.0070x over previous
#include <cuda_runtime.h>

// FocalBCELoss: loss = mean( -( t*log(p)*(1-p)^2*alpha[c] + (1-t)*log(1-p)*p^2 ) )
// N = 262144, C = 64, GAMMA = 2 (pow -> square). Single fused kernel:
// grid-stride partial sums -> last-block-done final reduction (deterministic).

#define N_ROWS   262144
#define N_COLS   64
#define TOTAL    (N_ROWS * N_COLS)          // 16,777,216 elements
#define TOTAL4   (TOTAL / 4)                // 4,194,304 float4s
#define NBLOCKS  1184                       // 148 SMs * 8
#define NTHREADS 256

__device__ float g_partials[NBLOCKS];
__device__ unsigned int g_ticket;           // zero-initialized; reset to 0 by last block

__global__ __launch_bounds__(NTHREADS) void focal_fused_kernel(
    const float* __restrict__ inputs,
    const float* __restrict__ targets,
    const float* __restrict__ alpha,
    float* __restrict__ out)
{
    __shared__ float s_alpha[N_COLS];
    __shared__ float s_warp[NTHREADS / 32];
    __shared__ bool  s_is_last;

    int tid = threadIdx.x;
    if (tid < N_COLS) s_alpha[tid] = alpha[tid];
    __syncthreads();

    const float4* in4 = (const float4*)inputs;
    const float4* tg4 = (const float4*)targets;

    float acc = 0.0f;

    for (int i = blockIdx.x * NTHREADS + tid; i < TOTAL4; i += NBLOCKS * NTHREADS) {
        float4 p = __ldcs(&in4[i]);
        float4 t = __ldcs(&tg4[i]);
        int c0 = (i * 4) & (N_COLS - 1);

        float a0 = s_alpha[c0 + 0];
        float a1 = s_alpha[c0 + 1];
        float a2 = s_alpha[c0 + 2];
        float a3 = s_alpha[c0 + 3];

        {
            float q = 1.0f - p.x;
            acc -= t.x * __logf(p.x) * q * q * a0
                 + (1.0f - t.x) * __logf(q) * p.x * p.x;
        }
        {
            float q = 1.0f - p.y;
            acc -= t.y * __logf(p.y) * q * q * a1
                 + (1.0f - t.y) * __logf(q) * p.y * p.y;
        }
        {
            float q = 1.0f - p.z;
            acc -= t.z * __logf(p.z) * q * q * a2
                 + (1.0f - t.z) * __logf(q) * p.z * p.z;
        }
        {
            float q = 1.0f - p.w;
            acc -= t.w * __logf(p.w) * q * q * a3
                 + (1.0f - t.w) * __logf(q) * p.w * p.w;
        }
    }

    // block reduce
    #pragma unroll
    for (int off = 16; off > 0; off >>= 1)
        acc += __shfl_down_sync(0xFFFFFFFFu, acc, off);

    int lane = tid & 31;
    int wid  = tid >> 5;
    if (lane == 0) s_warp[wid] = acc;
    __syncthreads();

    if (wid == 0) {
        float v = (lane < NTHREADS / 32) ? s_warp[lane] : 0.0f;
        #pragma unroll
        for (int off = 16; off > 0; off >>= 1)
            v += __shfl_down_sync(0xFFFFFFFFu, v, off);
        if (lane == 0) {
            g_partials[blockIdx.x] = v;
            __threadfence();
            unsigned int t = atomicInc(&g_ticket, NBLOCKS - 1);
            s_is_last = (t == NBLOCKS - 1);
        }
    }
    __syncthreads();

    // last-arriving block performs the final (deterministic, fixed-order) sum
    if (s_is_last) {
        float facc = 0.0f;
        for (int i = tid; i < NBLOCKS; i += NTHREADS)
            facc += g_partials[i];

        #pragma unroll
        for (int off = 16; off > 0; off >>= 1)
            facc += __shfl_down_sync(0xFFFFFFFFu, facc, off);

        if (lane == 0) s_warp[wid] = facc;
        __syncthreads();

        if (wid == 0) {
            float v = (lane < NTHREADS / 32) ? s_warp[lane] : 0.0f;
            #pragma unroll
            for (int off = 16; off > 0; off >>= 1)
                v += __shfl_down_sync(0xFFFFFFFFu, v, off);
            if (lane == 0) {
                out[0] = v * (1.0f / (float)TOTAL);
                g_ticket = 0;   // atomicInc wrapped to 0 already, but make it explicit
            }
        }
    }
}

extern "C" void kernel_launch(void* const* d_in, const int* in_sizes, int n_in,
                              void* d_out, int out_size)
{
    const float* inputs  = (const float*)d_in[0];
    const float* targets = (const float*)d_in[1];
    const float* alpha   = (const float*)d_in[2];
    float* out = (float*)d_out;

    focal_fused_kernel<<<NBLOCKS, NTHREADS>>>(inputs, targets, alpha, out);
}